// round 1
// baseline (speedup 1.0000x reference)
#include <cuda_runtime.h>
#include <cuda_bf16.h>
#include <cstdint>

// Problem constants (SheafGluingPoly: B=4, M=50000, D=8, E=1600000, POLY_K=3, LAM=1)
#define B_CONST 4
#define D_CONST 8
#define MAX_MBD 1600000   // B*M*D elements

// Ping-pong scratch for vertex state in transposed [m][b][d] layout (128B per vertex).
__device__ float g_bufA[MAX_MBD];
__device__ float g_bufB[MAX_MBD];

// ---------------------------------------------------------------------------
// init: v(A) = transpose(c0), out = pc[0]*c0, acc(B) = 0
// index space i over [m][b][d] (M*32)
// ---------------------------------------------------------------------------
__global__ void init_kernel(const float* __restrict__ c0,
                            const float* __restrict__ pc,
                            float* __restrict__ out,
                            float* __restrict__ v,
                            float* __restrict__ accz,
                            int M)
{
    int i = blockIdx.x * blockDim.x + threadIdx.x;
    int n = M * 32;
    if (i >= n) return;
    int m = i >> 5;
    int t = i & 31;
    int b = t >> 3;
    int d = t & 7;
    int src_idx = (b * M + m) * 8 + d;   // [b][m][d] layout of c0 / out
    float val = c0[src_idx];
    v[i] = val;
    out[src_idx] = pc[0] * val;
    accz[i] = 0.0f;
}

// ---------------------------------------------------------------------------
// edge kernel: one warp per edge. lane t = b*8 + d.
// Each lane holds column d of R_src[e] and R_dst[e] (8 regs each).
//   r[b][a] = sum_d ( Rs[a][d]*p_src[b][d] - Rd[a][d]*p_dst[b][d] )
//   acc[src][b][d] += sum_a Rs[a][d]*r[b][a]
//   acc[dst][b][d] -= sum_a Rd[a][d]*r[b][a]
// ---------------------------------------------------------------------------
__global__ void __launch_bounds__(256)
edge_kernel(const float* __restrict__ v,
            const int*   __restrict__ src,
            const int*   __restrict__ dst,
            const float* __restrict__ Rsrc,
            const float* __restrict__ Rdst,
            float*       __restrict__ acc,
            int E)
{
    int warp_id = (blockIdx.x * blockDim.x + threadIdx.x) >> 5;
    if (warp_id >= E) return;
    int t = threadIdx.x & 31;
    int d = t & 7;

    int s = __ldg(src + warp_id);
    int g = __ldg(dst + warp_id);

    float ps = __ldg(v + s * 32 + t);
    float pd = __ldg(v + g * 32 + t);

    const float* RsE = Rsrc + (int64_t)warp_id * 64;
    const float* RdE = Rdst + (int64_t)warp_id * 64;

    float rs[8], rd[8], z[8];
#pragma unroll
    for (int a = 0; a < 8; a++) {
        rs[a] = __ldg(RsE + a * 8 + d);   // Rs[a][d]
        rd[a] = __ldg(RdE + a * 8 + d);   // Rd[a][d]
    }

    // z[a] = Rs[a][d]*ps - Rd[a][d]*pd  (partial over this lane's d)
#pragma unroll
    for (int a = 0; a < 8; a++) {
        z[a] = fmaf(rs[a], ps, -rd[a] * pd);
    }

    // butterfly sum over the 8 lanes of this b-group -> full r[b][a] in every lane
#pragma unroll
    for (int sh = 1; sh <= 4; sh <<= 1) {
#pragma unroll
        for (int a = 0; a < 8; a++) {
            z[a] += __shfl_xor_sync(0xffffffffu, z[a], sh);
        }
    }

    // local transpose matvec: columns already in registers
    float cs = 0.0f, cd = 0.0f;
#pragma unroll
    for (int a = 0; a < 8; a++) {
        cs = fmaf(rs[a], z[a], cs);
        cd = fmaf(rd[a], z[a], cd);
    }

    atomicAdd(acc + s * 32 + t, cs);
    atomicAdd(acc + g * 32 + t, -cd);
}

// ---------------------------------------------------------------------------
// update: out[b][m][d] += pc[k] * acc[m][b][d]; optionally zero the other buffer
// (LAM == 1, so v_next is acc itself)
// ---------------------------------------------------------------------------
__global__ void update_kernel(const float* __restrict__ acc,
                              const float* __restrict__ pc,
                              int k,
                              float* __restrict__ out,
                              float* __restrict__ zother,
                              int M)
{
    int i = blockIdx.x * blockDim.x + threadIdx.x;
    int n = M * 32;
    if (i >= n) return;
    int m = i >> 5;
    int t = i & 31;
    int b = t >> 3;
    int d = t & 7;
    float val = acc[i];
    int oi = (b * M + m) * 8 + d;
    out[oi] += pc[k] * val;
    if (zother) zother[i] = 0.0f;
}

// ---------------------------------------------------------------------------
// launch
// ---------------------------------------------------------------------------
extern "C" void kernel_launch(void* const* d_in, const int* in_sizes, int n_in,
                              void* d_out, int out_size)
{
    const float* c0  = (const float*)d_in[0];
    const int*   src = (const int*)  d_in[1];
    const int*   dst = (const int*)  d_in[2];
    const float* Rs  = (const float*)d_in[3];
    const float* Rd  = (const float*)d_in[4];
    const float* pc  = (const float*)d_in[5];
    float* out = (float*)d_out;

    int E = in_sizes[1];                       // edges
    int M = in_sizes[0] / (B_CONST * D_CONST); // vertices

    float* bufA;
    float* bufB;
    cudaGetSymbolAddress((void**)&bufA, g_bufA);
    cudaGetSymbolAddress((void**)&bufB, g_bufB);

    int nV = M * 32;
    int tb = 256;
    int gV = (nV + tb - 1) / tb;
    int gE = (E * 32 + tb - 1) / tb;

    // out = pc[0]*c0 ; v = A = c0^T ; acc = B = 0
    init_kernel<<<gV, tb>>>(c0, pc, out, bufA, bufB, M);

    // k = 1: acc=B <- L(v=A); out += pc[1]*B; zero A
    edge_kernel<<<gE, tb>>>(bufA, src, dst, Rs, Rd, bufB, E);
    update_kernel<<<gV, tb>>>(bufB, pc, 1, out, bufA, M);

    // k = 2: acc=A <- L(v=B); out += pc[2]*A; zero B
    edge_kernel<<<gE, tb>>>(bufB, src, dst, Rs, Rd, bufA, E);
    update_kernel<<<gV, tb>>>(bufA, pc, 2, out, bufB, M);

    // k = 3: acc=B <- L(v=A); out += pc[3]*B
    edge_kernel<<<gE, tb>>>(bufA, src, dst, Rs, Rd, bufB, E);
    update_kernel<<<gV, tb>>>(bufB, pc, 3, out, nullptr, M);
}